// round 1
// baseline (speedup 1.0000x reference)
#include <cuda_runtime.h>
#include <math.h>

#define BN    737280      // total elements (8 * 92160)
#define NPIX  92160       // elements per (b,t) slice = 6*96*160
#define NTRK  512
#define NSEG  4096        // 8 * 512
#define NCH   66
#define THR   2.0f
#define DKS   0.05f

// ---------------- scratch (device globals; no allocation) ----------------
__device__ int           g_cnt[NSEG];
__device__ unsigned int  g_m1[NSEG];
__device__ float         g_z1[NSEG];
__device__ float         g_wc1[NSEG * 3];
__device__ unsigned int  g_m2[NSEG];
__device__ float         g_z2[NSEG];
__device__ float         g_wsum[NSEG * NCH];
__device__ int           g_rep[NSEG];
__device__ unsigned char g_flags[BN];

// ordered-uint mapping for float atomicMax (bijective, order-preserving)
__device__ __forceinline__ unsigned int fok(float f) {
    unsigned int b = __float_as_uint(f);
    return (b & 0x80000000u) ? ~b : (b | 0x80000000u);
}
__device__ __forceinline__ float kof(unsigned int u) {
    unsigned int b = (u & 0x80000000u) ? (u & 0x7FFFFFFFu) : ~u;
    return __uint_as_float(b);
}

__device__ __forceinline__ int seg_of(int i, int gid) {
    return (i / NPIX) * NTRK + gid;
}

// ---------------- kernels ----------------
__global__ void k_init() {
    int i = blockIdx.x * blockDim.x + threadIdx.x;
    if (i < NSEG * NCH) g_wsum[i] = 0.0f;
    if (i < NSEG) {
        g_cnt[i] = 0;
        g_m1[i]  = 0u;
        g_z1[i]  = 0.0f;
        g_wc1[3 * i + 0] = 0.0f;
        g_wc1[3 * i + 1] = 0.0f;
        g_wc1[3 * i + 2] = 0.0f;
        g_m2[i]  = 0u;
        g_z2[i]  = 0.0f;
        g_rep[i] = 0x7FFFFFFF;
    }
}

__global__ void k_count(const float* __restrict__ kp, const int* __restrict__ gid) {
    int i = blockIdx.x * blockDim.x + threadIdx.x;
    if (i >= BN) return;
    int g = gid[i];
    if (g < 0) return;
    int s = seg_of(i, g);
    atomicAdd(&g_cnt[s], 1);
    atomicMax(&g_m1[s], fok(kp[i]));
}

__global__ void k_soft1(const float* __restrict__ cen, const float* __restrict__ kp,
                        const int* __restrict__ gid) {
    int i = blockIdx.x * blockDim.x + threadIdx.x;
    if (i >= BN) return;
    int g = gid[i];
    if (g < 0) return;
    int s = seg_of(i, g);
    float m = kof(g_m1[s]);
    float e = expf(kp[i] - m);
    atomicAdd(&g_z1[s], e);
    atomicAdd(&g_wc1[3 * s + 0], e * cen[3 * i + 0]);
    atomicAdd(&g_wc1[3 * s + 1], e * cen[3 * i + 1]);
    atomicAdd(&g_wc1[3 * s + 2], e * cen[3 * i + 2]);
}

__global__ void k_dist(const float* __restrict__ cen, const float* __restrict__ kp,
                       const int* __restrict__ gid) {
    int i = blockIdx.x * blockDim.x + threadIdx.x;
    if (i >= BN) return;
    unsigned char f = 0;
    int g = gid[i];
    if (g >= 0) {
        int s = seg_of(i, g);
        if (g_cnt[s] >= 2) {
            float zinv = 1.0f / fmaxf(g_z1[s], 1e-20f);
            float dx = cen[3 * i + 0] - g_wc1[3 * s + 0] * zinv;
            float dy = cen[3 * i + 1] - g_wc1[3 * s + 1] * zinv;
            float dz = cen[3 * i + 2] - g_wc1[3 * s + 2] * zinv;
            float dist = sqrtf(dx * dx + dy * dy + dz * dz);
            if (dist <= THR) {
                f = 1;
                atomicMax(&g_m2[s], fok(kp[i]));
            }
        }
    }
    g_flags[i] = f;
}

__global__ void __launch_bounds__(256)
k_accum(const float* __restrict__ cen, const float* __restrict__ off,
        const float* __restrict__ opa, const float* __restrict__ sca,
        const float* __restrict__ rot, const float* __restrict__ fdc,
        const float* __restrict__ kp,  const float* __restrict__ ins,
        const float* __restrict__ mot, const int* __restrict__ gid,
        float* __restrict__ out) {
    int i = blockIdx.x * blockDim.x + threadIdx.x;
    if (i >= BN) return;

    float buf[NCH];
    // channel order: center(0-2) offset(3-5) opacity(6) scale(7-9) rotation(10-13)
    //                feat_dc(14-16) keep(17) inst(18-49) motion(50-65)
    #pragma unroll
    for (int c = 0; c < 3; c++) buf[c] = cen[3 * i + c];
    #pragma unroll
    for (int c = 0; c < 3; c++) buf[3 + c] = off[3 * i + c];
    buf[6] = opa[i];
    #pragma unroll
    for (int c = 0; c < 3; c++) buf[7 + c] = sca[3 * i + c];
    {
        float4 r4 = reinterpret_cast<const float4*>(rot)[i];
        buf[10] = r4.x; buf[11] = r4.y; buf[12] = r4.z; buf[13] = r4.w;
    }
    #pragma unroll
    for (int c = 0; c < 3; c++) buf[14 + c] = fdc[3 * i + c];
    buf[17] = kp[i];
    {
        const float4* ip = reinterpret_cast<const float4*>(ins) + (size_t)i * 8;
        #pragma unroll
        for (int q = 0; q < 8; q++) {
            float4 v = ip[q];
            buf[18 + 4 * q + 0] = v.x; buf[18 + 4 * q + 1] = v.y;
            buf[18 + 4 * q + 2] = v.z; buf[18 + 4 * q + 3] = v.w;
        }
    }
    {
        const float4* mp = reinterpret_cast<const float4*>(mot) + (size_t)i * 4;
        #pragma unroll
        for (int q = 0; q < 4; q++) {
            float4 v = mp[q];
            buf[50 + 4 * q + 0] = v.x; buf[50 + 4 * q + 1] = v.y;
            buf[50 + 4 * q + 2] = v.z; buf[50 + 4 * q + 3] = v.w;
        }
    }

    if (g_flags[i]) {
        int s = seg_of(i, gid[i]);
        float k0  = buf[17];
        float m2f = kof(g_m2[s]);
        float e   = expf(k0 - m2f);
        atomicAdd(&g_z2[s], e);
        float* ws = &g_wsum[(size_t)s * NCH];
        #pragma unroll
        for (int c = 0; c < NCH; c++) atomicAdd(&ws[c], e * buf[c]);
        if (k0 == m2f) atomicMin(&g_rep[s], i);
    } else {
        float* o = out + (size_t)i * NCH;
        #pragma unroll
        for (int c = 0; c < NCH; c++) o[c] = buf[c];
    }
}

__global__ void __launch_bounds__(256)
k_final(const int* __restrict__ gid, float* __restrict__ out) {
    int i = blockIdx.x * blockDim.x + threadIdx.x;
    if (i >= BN) return;
    if (!g_flags[i]) return;
    int s = seg_of(i, gid[i]);
    float zinv = 1.0f / fmaxf(g_z2[s], 1e-20f);
    const float* ws = &g_wsum[(size_t)s * NCH];

    float buf[NCH];
    #pragma unroll
    for (int c = 0; c < NCH; c++) buf[c] = ws[c] * zinv;

    // normalize rotation (scale-invariant, same as normalizing the raw segment sum)
    float nr = sqrtf(buf[10] * buf[10] + buf[11] * buf[11] +
                     buf[12] * buf[12] + buf[13] * buf[13]);
    float rinv = 1.0f / fmaxf(nr, 1e-12f);
    buf[10] *= rinv; buf[11] *= rinv; buf[12] *= rinv; buf[13] *= rinv;

    float sfac = (i == g_rep[s]) ? 1.0f : DKS;
    buf[6]  *= sfac;                 // opacity
    buf[17]  = kof(g_m2[s]) * sfac;  // mkeep == segment max of keep == m2

    float* o = out + (size_t)i * NCH;
    #pragma unroll
    for (int c = 0; c < NCH; c++) o[c] = buf[c];
}

// ---------------- launcher ----------------
extern "C" void kernel_launch(void* const* d_in, const int* in_sizes, int n_in,
                              void* d_out, int out_size) {
    const float* cen = (const float*)d_in[0];
    const float* off = (const float*)d_in[1];
    const float* opa = (const float*)d_in[2];
    const float* sca = (const float*)d_in[3];
    const float* rot = (const float*)d_in[4];
    const float* fdc = (const float*)d_in[5];
    const float* kp  = (const float*)d_in[6];
    const float* ins = (const float*)d_in[7];
    const float* mot = (const float*)d_in[8];
    const int*   gid = (const int*)d_in[9];
    float* out = (float*)d_out;

    const int TB = 256;
    const int GB = (BN + TB - 1) / TB;       // 2880
    const int GI = (NSEG * NCH + TB - 1) / TB;

    k_init <<<GI, TB>>>();
    k_count<<<GB, TB>>>(kp, gid);
    k_soft1<<<GB, TB>>>(cen, kp, gid);
    k_dist <<<GB, TB>>>(cen, kp, gid);
    k_accum<<<GB, TB>>>(cen, off, opa, sca, rot, fdc, kp, ins, mot, gid, out);
    k_final<<<GB, TB>>>(gid, out);
}

// round 2
// speedup vs baseline: 2.1975x; 2.1975x over previous
#include <cuda_runtime.h>
#include <math.h>

#define BN    737280      // total elements (8 * 92160)
#define NPIX  92160       // elements per (b,t) slice = 6*96*160
#define NTRK  512
#define NSEG  4096        // 8 * 512
#define NCH   66
#define WCH   68          // padded accumulator row: 66 ch + z2 + pad (16B-aligned stride)
#define THR   2.0f
#define DKS   0.05f

// ---------------- scratch (device globals; no allocation) ----------------
__device__ int                        g_cnt[NSEG];
__device__ unsigned int               g_m1[NSEG];
__device__ __align__(16) float4       g_p1[NSEG];          // {z1, wc1x, wc1y, wc1z}
__device__ unsigned int               g_m2[NSEG];
__device__ __align__(16) float        g_wsum[NSEG * WCH];  // [s][0..65]=ch sums, [s][66]=z2
__device__ int                        g_rep[NSEG];
__device__ unsigned char              g_flags[BN];

// ordered-uint mapping for float atomicMax (bijective, order-preserving)
__device__ __forceinline__ unsigned int fok(float f) {
    unsigned int b = __float_as_uint(f);
    return (b & 0x80000000u) ? ~b : (b | 0x80000000u);
}
__device__ __forceinline__ float kof(unsigned int u) {
    unsigned int b = (u & 0x80000000u) ? (u & 0x7FFFFFFFu) : ~u;
    return __uint_as_float(b);
}

__device__ __forceinline__ int seg_of(int i, int gid) {
    return (i / NPIX) * NTRK + gid;
}

// vectorized global reductions (sm_90+)
__device__ __forceinline__ void red_add_v4(float* p, float a, float b, float c, float d) {
    asm volatile("red.global.add.v4.f32 [%0], {%1, %2, %3, %4};"
                 :: "l"(p), "f"(a), "f"(b), "f"(c), "f"(d) : "memory");
}

// ---------------- kernels ----------------
__global__ void k_init() {
    int i = blockIdx.x * blockDim.x + threadIdx.x;
    if (i < NSEG * WCH) g_wsum[i] = 0.0f;
    if (i < NSEG) {
        g_cnt[i] = 0;
        g_m1[i]  = 0u;
        g_p1[i]  = make_float4(0.f, 0.f, 0.f, 0.f);
        g_m2[i]  = 0u;
        g_rep[i] = 0x7FFFFFFF;
    }
}

__global__ void k_count(const float* __restrict__ kp, const int* __restrict__ gid) {
    int i = blockIdx.x * blockDim.x + threadIdx.x;
    if (i >= BN) return;
    int g = gid[i];
    if (g < 0) return;
    int s = seg_of(i, g);
    atomicAdd(&g_cnt[s], 1);
    atomicMax(&g_m1[s], fok(kp[i]));
}

__global__ void k_soft1(const float* __restrict__ cen, const float* __restrict__ kp,
                        const int* __restrict__ gid) {
    int i = blockIdx.x * blockDim.x + threadIdx.x;
    if (i >= BN) return;
    int g = gid[i];
    if (g < 0) return;
    int s = seg_of(i, g);
    float m = kof(g_m1[s]);
    float e = expf(kp[i] - m);
    red_add_v4(&g_p1[s].x, e, e * cen[3 * i + 0], e * cen[3 * i + 1], e * cen[3 * i + 2]);
}

__global__ void k_dist(const float* __restrict__ cen, const float* __restrict__ kp,
                       const int* __restrict__ gid) {
    int i = blockIdx.x * blockDim.x + threadIdx.x;
    if (i >= BN) return;
    unsigned char f = 0;
    int g = gid[i];
    if (g >= 0) {
        int s = seg_of(i, g);
        if (g_cnt[s] >= 2) {
            float4 p = g_p1[s];
            float zinv = 1.0f / fmaxf(p.x, 1e-20f);
            float dx = cen[3 * i + 0] - p.y * zinv;
            float dy = cen[3 * i + 1] - p.z * zinv;
            float dz = cen[3 * i + 2] - p.w * zinv;
            float dist = sqrtf(dx * dx + dy * dy + dz * dz);
            if (dist <= THR) {
                f = 1;
                atomicMax(&g_m2[s], fok(kp[i]));
            }
        }
    }
    g_flags[i] = f;
}

__global__ void __launch_bounds__(256)
k_accum(const float* __restrict__ cen, const float* __restrict__ off,
        const float* __restrict__ opa, const float* __restrict__ sca,
        const float* __restrict__ rot, const float* __restrict__ fdc,
        const float* __restrict__ kp,  const float* __restrict__ ins,
        const float* __restrict__ mot, const int* __restrict__ gid,
        float* __restrict__ out) {
    int i = blockIdx.x * blockDim.x + threadIdx.x;
    if (i >= BN) return;

    float buf[NCH];
    // channel order: center(0-2) offset(3-5) opacity(6) scale(7-9) rotation(10-13)
    //                feat_dc(14-16) keep(17) inst(18-49) motion(50-65)
    #pragma unroll
    for (int c = 0; c < 3; c++) buf[c] = cen[3 * i + c];
    #pragma unroll
    for (int c = 0; c < 3; c++) buf[3 + c] = off[3 * i + c];
    buf[6] = opa[i];
    #pragma unroll
    for (int c = 0; c < 3; c++) buf[7 + c] = sca[3 * i + c];
    {
        float4 r4 = reinterpret_cast<const float4*>(rot)[i];
        buf[10] = r4.x; buf[11] = r4.y; buf[12] = r4.z; buf[13] = r4.w;
    }
    #pragma unroll
    for (int c = 0; c < 3; c++) buf[14 + c] = fdc[3 * i + c];
    buf[17] = kp[i];
    {
        const float4* ip = reinterpret_cast<const float4*>(ins) + (size_t)i * 8;
        #pragma unroll
        for (int q = 0; q < 8; q++) {
            float4 v = ip[q];
            buf[18 + 4 * q + 0] = v.x; buf[18 + 4 * q + 1] = v.y;
            buf[18 + 4 * q + 2] = v.z; buf[18 + 4 * q + 3] = v.w;
        }
    }
    {
        const float4* mp = reinterpret_cast<const float4*>(mot) + (size_t)i * 4;
        #pragma unroll
        for (int q = 0; q < 4; q++) {
            float4 v = mp[q];
            buf[50 + 4 * q + 0] = v.x; buf[50 + 4 * q + 1] = v.y;
            buf[50 + 4 * q + 2] = v.z; buf[50 + 4 * q + 3] = v.w;
        }
    }

    if (g_flags[i]) {
        int s = seg_of(i, gid[i]);
        float k0  = buf[17];
        float m2f = kof(g_m2[s]);
        float e   = expf(k0 - m2f);
        float* ws = &g_wsum[(size_t)s * WCH];
        // 16 x red.v4 for channels 0..63, 1 x red.v4 for {ch64, ch65, z2, pad}
        #pragma unroll
        for (int q = 0; q < 16; q++) {
            red_add_v4(ws + 4 * q,
                       e * buf[4 * q + 0], e * buf[4 * q + 1],
                       e * buf[4 * q + 2], e * buf[4 * q + 3]);
        }
        red_add_v4(ws + 64, e * buf[64], e * buf[65], e, 0.0f);
        if (k0 == m2f) atomicMin(&g_rep[s], i);
    } else {
        // rows are 8B-aligned (264 % 8 == 0): write as 33 x float2
        float2* o = reinterpret_cast<float2*>(out + (size_t)i * NCH);
        #pragma unroll
        for (int c = 0; c < NCH / 2; c++)
            o[c] = make_float2(buf[2 * c], buf[2 * c + 1]);
    }
}

__global__ void __launch_bounds__(256)
k_final(const int* __restrict__ gid, float* __restrict__ out) {
    int i = blockIdx.x * blockDim.x + threadIdx.x;
    if (i >= BN) return;
    if (!g_flags[i]) return;
    int s = seg_of(i, gid[i]);
    const float* ws = &g_wsum[(size_t)s * WCH];
    float zinv = 1.0f / fmaxf(ws[66], 1e-20f);

    float buf[NCH];
    #pragma unroll
    for (int c = 0; c < NCH; c++) buf[c] = ws[c] * zinv;

    // normalize rotation (scale-invariant, same as normalizing the raw segment sum)
    float nr = sqrtf(buf[10] * buf[10] + buf[11] * buf[11] +
                     buf[12] * buf[12] + buf[13] * buf[13]);
    float rinv = 1.0f / fmaxf(nr, 1e-12f);
    buf[10] *= rinv; buf[11] *= rinv; buf[12] *= rinv; buf[13] *= rinv;

    float sfac = (i == g_rep[s]) ? 1.0f : DKS;
    buf[6]  *= sfac;                 // opacity
    buf[17]  = kof(g_m2[s]) * sfac;  // mkeep == segment max of keep == m2

    float2* o = reinterpret_cast<float2*>(out + (size_t)i * NCH);
    #pragma unroll
    for (int c = 0; c < NCH / 2; c++)
        o[c] = make_float2(buf[2 * c], buf[2 * c + 1]);
}

// ---------------- launcher ----------------
extern "C" void kernel_launch(void* const* d_in, const int* in_sizes, int n_in,
                              void* d_out, int out_size) {
    const float* cen = (const float*)d_in[0];
    const float* off = (const float*)d_in[1];
    const float* opa = (const float*)d_in[2];
    const float* sca = (const float*)d_in[3];
    const float* rot = (const float*)d_in[4];
    const float* fdc = (const float*)d_in[5];
    const float* kp  = (const float*)d_in[6];
    const float* ins = (const float*)d_in[7];
    const float* mot = (const float*)d_in[8];
    const int*   gid = (const int*)d_in[9];
    float* out = (float*)d_out;

    const int TB = 256;
    const int GB = (BN + TB - 1) / TB;            // 2880
    const int GI = (NSEG * WCH + TB - 1) / TB;

    k_init <<<GI, TB>>>();
    k_count<<<GB, TB>>>(kp, gid);
    k_soft1<<<GB, TB>>>(cen, kp, gid);
    k_dist <<<GB, TB>>>(cen, kp, gid);
    k_accum<<<GB, TB>>>(cen, off, opa, sca, rot, fdc, kp, ins, mot, gid, out);
    k_final<<<GB, TB>>>(gid, out);
}

// round 3
// speedup vs baseline: 3.2064x; 1.4591x over previous
#include <cuda_runtime.h>
#include <math.h>

#define BN    737280      // total elements (8 * 92160)
#define NPIX  92160       // elements per (b,t) slice = 6*96*160
#define NTRK  512
#define NSEG  4096        // 8 * 512
#define NCH   66
#define WCH   68          // padded accumulator row (16B-aligned stride)
#define THR   2.0f
#define DKS   0.05f

// ---------------- scratch (device globals; no allocation) ----------------
__device__ int                        g_cnt[NSEG];
__device__ __align__(16) float4       g_p1[NSEG];           // {z1, wc1x, wc1y, wc1z}
__device__ unsigned long long         g_repkey[NSEG];       // (~fok(k0))<<32 | idx
__device__ __align__(16) float        g_wsum[NSEG * WCH];   // [0..65]=w*ch, [66]=z2
__device__ __align__(16) float        g_srow[NSEG * WCH];   // finalized segment row
__device__ int                        g_rep[NSEG];
__device__ unsigned char              g_flags[BN];

// ordered-uint mapping for floats (bijective, order-preserving)
__device__ __forceinline__ unsigned int fok(float f) {
    unsigned int b = __float_as_uint(f);
    return (b & 0x80000000u) ? ~b : (b | 0x80000000u);
}
__device__ __forceinline__ float kof(unsigned int u) {
    unsigned int b = (u & 0x80000000u) ? (u & 0x7FFFFFFFu) : ~u;
    return __uint_as_float(b);
}
__device__ __forceinline__ int seg_of(int i, int g) {
    return (i / NPIX) * NTRK + g;
}
__device__ __forceinline__ void red_add_v4(float* p, float a, float b, float c, float d) {
    asm volatile("red.global.add.v4.f32 [%0], {%1, %2, %3, %4};"
                 :: "l"(p), "f"(a), "f"(b), "f"(c), "f"(d) : "memory");
}

// load all 66 channels for element i into buf
// order: center(0-2) offset(3-5) opacity(6) scale(7-9) rotation(10-13)
//        feat_dc(14-16) keep(17) inst(18-49) motion(50-65)
__device__ __forceinline__ void load_row(
    int i, float* buf,
    const float* __restrict__ cen, const float* __restrict__ off,
    const float* __restrict__ opa, const float* __restrict__ sca,
    const float* __restrict__ rot, const float* __restrict__ fdc,
    const float* __restrict__ kp,  const float* __restrict__ ins,
    const float* __restrict__ mot) {
    #pragma unroll
    for (int c = 0; c < 3; c++) buf[c]      = cen[3 * i + c];
    #pragma unroll
    for (int c = 0; c < 3; c++) buf[3 + c]  = off[3 * i + c];
    buf[6] = opa[i];
    #pragma unroll
    for (int c = 0; c < 3; c++) buf[7 + c]  = sca[3 * i + c];
    {
        float4 r4 = reinterpret_cast<const float4*>(rot)[i];
        buf[10] = r4.x; buf[11] = r4.y; buf[12] = r4.z; buf[13] = r4.w;
    }
    #pragma unroll
    for (int c = 0; c < 3; c++) buf[14 + c] = fdc[3 * i + c];
    buf[17] = kp[i];
    const float4* ip = reinterpret_cast<const float4*>(ins) + (size_t)i * 8;
    #pragma unroll
    for (int q = 0; q < 8; q++) {
        float4 v = ip[q];
        buf[18 + 4 * q + 0] = v.x; buf[18 + 4 * q + 1] = v.y;
        buf[18 + 4 * q + 2] = v.z; buf[18 + 4 * q + 3] = v.w;
    }
    const float4* mp = reinterpret_cast<const float4*>(mot) + (size_t)i * 4;
    #pragma unroll
    for (int q = 0; q < 4; q++) {
        float4 v = mp[q];
        buf[50 + 4 * q + 0] = v.x; buf[50 + 4 * q + 1] = v.y;
        buf[50 + 4 * q + 2] = v.z; buf[50 + 4 * q + 3] = v.w;
    }
}

// ---------------- kernels ----------------
__global__ void k_init() {
    int i = blockIdx.x * blockDim.x + threadIdx.x;
    if (i < NSEG * WCH) g_wsum[i] = 0.0f;
    if (i < NSEG) {
        g_cnt[i]    = 0;
        g_p1[i]     = make_float4(0.f, 0.f, 0.f, 0.f);
        g_repkey[i] = 0xFFFFFFFFFFFFFFFFull;
    }
}

// count + phase-1 softmax sums (no max subtraction: exp(k0) directly)
__global__ void k1(const float* __restrict__ cen, const float* __restrict__ kp,
                   const int* __restrict__ gid) {
    int i = blockIdx.x * blockDim.x + threadIdx.x;
    if (i >= BN) return;
    int g = gid[i];
    if (g < 0) return;
    int s = seg_of(i, g);
    atomicAdd(&g_cnt[s], 1);
    float e = __expf(kp[i]);
    red_add_v4(&g_p1[s].x, e, e * cen[3 * i + 0], e * cen[3 * i + 1], e * cen[3 * i + 2]);
}

// activity + weighted accumulation + representative key
__global__ void __launch_bounds__(256)
k2(const float* __restrict__ cen, const float* __restrict__ off,
   const float* __restrict__ opa, const float* __restrict__ sca,
   const float* __restrict__ rot, const float* __restrict__ fdc,
   const float* __restrict__ kp,  const float* __restrict__ ins,
   const float* __restrict__ mot, const int* __restrict__ gid) {
    int i = blockIdx.x * blockDim.x + threadIdx.x;
    if (i >= BN) return;
    int g = gid[i];
    int s = 0;
    unsigned char f = 0;
    float k0 = 0.0f;
    if (g >= 0) {
        s = seg_of(i, g);
        if (g_cnt[s] >= 2) {
            float4 p = g_p1[s];
            float zinv = 1.0f / fmaxf(p.x, 1e-20f);
            float dx = cen[3 * i + 0] - p.y * zinv;
            float dy = cen[3 * i + 1] - p.z * zinv;
            float dz = cen[3 * i + 2] - p.w * zinv;
            if (sqrtf(dx * dx + dy * dy + dz * dz) <= THR) {
                f = 1;
                k0 = kp[i];
            }
        }
    }
    g_flags[i] = f;
    if (!f) return;

    float buf[NCH];
    load_row(i, buf, cen, off, opa, sca, rot, fdc, kp, ins, mot);
    float e = __expf(k0);
    float* ws = &g_wsum[(size_t)s * WCH];
    #pragma unroll
    for (int q = 0; q < 16; q++)
        red_add_v4(ws + 4 * q,
                   e * buf[4 * q + 0], e * buf[4 * q + 1],
                   e * buf[4 * q + 2], e * buf[4 * q + 3]);
    red_add_v4(ws + 64, e * buf[64], e * buf[65], e, 0.0f);

    unsigned long long key =
        ((unsigned long long)(~fok(k0)) << 32) | (unsigned int)i;
    atomicMin(&g_repkey[s], key);
}

// finalize one output row per segment (means, rotation norm, mkeep, rep idx)
__global__ void k_seg() {
    int s = blockIdx.x * blockDim.x + threadIdx.x;
    if (s >= NSEG) return;
    const float* ws = &g_wsum[(size_t)s * WCH];
    float* r = &g_srow[(size_t)s * WCH];
    float zinv = 1.0f / fmaxf(ws[66], 1e-20f);
    float row[NCH];
    #pragma unroll
    for (int c = 0; c < NCH; c++) row[c] = ws[c] * zinv;
    float nr = sqrtf(row[10] * row[10] + row[11] * row[11] +
                     row[12] * row[12] + row[13] * row[13]);
    float rinv = 1.0f / fmaxf(nr, 1e-12f);
    row[10] *= rinv; row[11] *= rinv; row[12] *= rinv; row[13] *= rinv;

    unsigned long long key = g_repkey[s];
    g_rep[s] = (int)(unsigned int)(key & 0xFFFFFFFFull);
    row[17] = kof(~(unsigned int)(key >> 32));  // m2 = segment max keep
    #pragma unroll
    for (int c = 0; c < NCH; c++) r[c] = row[c];
}

// output: gather (segment row for active, raw channels for inactive),
// stage in smem, write fully coalesced
__global__ void __launch_bounds__(128)
k3(const float* __restrict__ cen, const float* __restrict__ off,
   const float* __restrict__ opa, const float* __restrict__ sca,
   const float* __restrict__ rot, const float* __restrict__ fdc,
   const float* __restrict__ kp,  const float* __restrict__ ins,
   const float* __restrict__ mot, const int* __restrict__ gid,
   float* __restrict__ out) {
    __shared__ float stage[128 * NCH];   // 33,792 B
    int tid = threadIdx.x;
    int i = blockIdx.x * 128 + tid;

    float buf[NCH];
    if (g_flags[i]) {
        int s = seg_of(i, gid[i]);
        const float* r = &g_srow[(size_t)s * WCH];
        #pragma unroll
        for (int c = 0; c < NCH; c++) buf[c] = r[c];
        float sfac = (i == g_rep[s]) ? 1.0f : DKS;
        buf[6]  *= sfac;
        buf[17] *= sfac;
    } else {
        load_row(i, buf, cen, off, opa, sca, rot, fdc, kp, ins, mot);
    }
    #pragma unroll
    for (int c = 0; c < NCH; c++) stage[tid * NCH + c] = buf[c];
    __syncthreads();

    // block writes contiguous range out[blockIdx*128*66 .. +128*66), 16B-aligned
    float4* dst = reinterpret_cast<float4*>(out + (size_t)blockIdx.x * 128 * NCH);
    const float4* src = reinterpret_cast<const float4*>(stage);
    #pragma unroll
    for (int q = 0; q < (128 * NCH) / 4 / 128; q++)   // 16.5 -> handled below
        ;
    for (int idx = tid; idx < (128 * NCH) / 4; idx += 128)
        dst[idx] = src[idx];
}

// ---------------- launcher ----------------
extern "C" void kernel_launch(void* const* d_in, const int* in_sizes, int n_in,
                              void* d_out, int out_size) {
    const float* cen = (const float*)d_in[0];
    const float* off = (const float*)d_in[1];
    const float* opa = (const float*)d_in[2];
    const float* sca = (const float*)d_in[3];
    const float* rot = (const float*)d_in[4];
    const float* fdc = (const float*)d_in[5];
    const float* kp  = (const float*)d_in[6];
    const float* ins = (const float*)d_in[7];
    const float* mot = (const float*)d_in[8];
    const int*   gid = (const int*)d_in[9];
    float* out = (float*)d_out;

    const int TB = 256;
    const int GB = (BN + TB - 1) / TB;            // 2880
    const int GI = (NSEG * WCH + TB - 1) / TB;    // 1088

    k_init<<<GI, TB>>>();
    k1    <<<GB, TB>>>(cen, kp, gid);
    k2    <<<GB, TB>>>(cen, off, opa, sca, rot, fdc, kp, ins, mot, gid);
    k_seg <<<NSEG / TB, TB>>>();
    k3    <<<BN / 128, 128>>>(cen, off, opa, sca, rot, fdc, kp, ins, mot, gid, out);
}